// round 5
// baseline (speedup 1.0000x reference)
#include <cuda_runtime.h>
#include <cuda_fp16.h>
#include <math.h>
#include <stdint.h>

// LLTM, compute_103 baseline PTX (no tcgen05 in this toolchain path).
// gates = concat(old_h, input) @ W + bias, fused activations.
// GEMM = fp16 hi-term (xh*wh) + ONE int8 GEMM for both cross terms:
//   A' = [ int8(xl*SL) | int8(x*S8) ],  B' = [ int8(w*S8) | int8(wl*SL) ]  (k-concat, shared scale SL*S8)
//   gates ~= fp32(xh*wh) + s32(A'.B') / (SL*S8)
// mma.m16n8k16.f16 + mma.m16n8k32.s8 + ldmatrix + cp.async 4-stage pipeline.
// CTA tile 128m x 96n, n gate-planar -> register-fused epilogue.
// Shapes: B=4096, F=2048, S=2048, K=4096, N=6144.

#define S_DIM 2048
#define B_DIM 4096
#define K_DIM 4096
#define N_DIM 6144
#define BK    32              // fp16 k per stage (=64B row); int8 row also 64B (k64)
#define NITER (K_DIM / BK)    // 128
#define STAGES 4

#define QS8  21.0f
#define QSL  64000.0f
#define INV_SS (1.0f / (21.0f * 64000.0f))

// smem: 4 tiles, 64B rows padded to 80B stride (conflict-free ldmatrix).
#define RSB      80
#define OFF_AH   0            // fp16 A, 128 rows
#define OFF_AI   10240        // int8 A, 128 rows
#define OFF_BH   20480        // fp16 B, 96 rows
#define OFF_BI   28160        // int8 B, 96 rows
#define STAGE_SZ 35840
#define SMEM_TOTAL (STAGES * STAGE_SZ)   // 143360

// ---------------- device scratch ----------------
__device__ __half  g_Wh[(size_t)N_DIM * K_DIM];
__device__ int8_t  g_WC[(size_t)N_DIM * 2 * K_DIM];   // [n][0..K): w*S8, [K..2K): wl*SL
__device__ __half  g_Xh[(size_t)B_DIM * K_DIM];
__device__ int8_t  g_XC[(size_t)B_DIM * 2 * K_DIM];   // [b][0..K): xl*SL, [K..2K): x*S8

// ---------------- helpers ----------------
__device__ __forceinline__ uint32_t smem_u32(const void* p) {
    uint32_t a;
    asm("{ .reg .u64 t; cvta.to.shared.u64 t, %1; cvt.u32.u64 %0, t; }" : "=r"(a) : "l"(p));
    return a;
}
__device__ __forceinline__ void cp_async16(uint32_t sdst, const void* gsrc) {
    asm volatile("cp.async.cg.shared.global [%0], [%1], 16;" :: "r"(sdst), "l"(gsrc) : "memory");
}
__device__ __forceinline__ void cp_commit() {
    asm volatile("cp.async.commit_group;" ::: "memory");
}
__device__ __forceinline__ void cp_wait2() {
    asm volatile("cp.async.wait_group 2;" ::: "memory");
}
__device__ __forceinline__ void ldsm_x4(uint32_t& r0, uint32_t& r1, uint32_t& r2, uint32_t& r3,
                                        uint32_t addr) {
    asm volatile("ldmatrix.sync.aligned.m8n8.x4.shared.b16 {%0,%1,%2,%3}, [%4];"
                 : "=r"(r0), "=r"(r1), "=r"(r2), "=r"(r3) : "r"(addr));
}
__device__ __forceinline__ void mma16816(float* c, const uint32_t* a, uint32_t b0, uint32_t b1) {
    asm volatile("mma.sync.aligned.m16n8k16.row.col.f32.f16.f16.f32 "
                 "{%0,%1,%2,%3}, {%4,%5,%6,%7}, {%8,%9}, {%0,%1,%2,%3};"
                 : "+f"(c[0]), "+f"(c[1]), "+f"(c[2]), "+f"(c[3])
                 : "r"(a[0]), "r"(a[1]), "r"(a[2]), "r"(a[3]), "r"(b0), "r"(b1));
}
__device__ __forceinline__ void imma16832(int* c, const uint32_t* a, uint32_t b0, uint32_t b1) {
    asm volatile("mma.sync.aligned.m16n8k32.row.col.s32.s8.s8.s32 "
                 "{%0,%1,%2,%3}, {%4,%5,%6,%7}, {%8,%9}, {%0,%1,%2,%3};"
                 : "+r"(c[0]), "+r"(c[1]), "+r"(c[2]), "+r"(c[3])
                 : "r"(a[0]), "r"(a[1]), "r"(a[2]), "r"(a[3]), "r"(b0), "r"(b1));
}
__device__ __forceinline__ int8_t q8(float v, float s) {
    int r = __float2int_rn(v * s);
    r = max(-127, min(127, r));
    return (int8_t)r;
}

// ---------------- pre-pass: X = concat(old_h, input) -> Xh fp16, XC int8 ----------------
__global__ __launch_bounds__(256) void split_x_kernel(const float* __restrict__ input,
                                                      const float* __restrict__ old_h) {
    size_t idx = ((size_t)blockIdx.x * blockDim.x + threadIdx.x) * 4;
    int b = (int)(idx / K_DIM);
    int k = (int)(idx % K_DIM);
    const float* src = (k < S_DIM) ? old_h + (size_t)b * S_DIM + k
                                   : input + (size_t)b * (K_DIM - S_DIM) + (k - S_DIM);
    float4 v = *(const float4*)src;
    float vv[4] = {v.x, v.y, v.z, v.w};
    union { __half h[4]; uint2 u; } hi;
    uchar4 lo8, hi8;
    unsigned char* lp = (unsigned char*)&lo8;
    unsigned char* hp = (unsigned char*)&hi8;
    #pragma unroll
    for (int e = 0; e < 4; e++) {
        hi.h[e] = __float2half_rn(vv[e]);
        float r = vv[e] - __half2float(hi.h[e]);
        lp[e] = (unsigned char)q8(r, QSL);
        hp[e] = (unsigned char)q8(vv[e], QS8);
    }
    *(uint2*)&g_Xh[idx] = hi.u;
    size_t rowb = (size_t)b * (2 * K_DIM);
    *(uchar4*)&g_XC[rowb + k] = lo8;            // xl*SL in [0..K)
    *(uchar4*)&g_XC[rowb + K_DIM + k] = hi8;    // x*S8  in [K..2K)
}

// ---------------- pre-pass: transpose W[K,N] -> Wh fp16 [N,K], WC int8 [N,2K] ----------------
__global__ __launch_bounds__(256) void split_w_kernel(const float* __restrict__ W) {
    __shared__ float sh[32][33];
    int n0 = blockIdx.x * 32;
    int k0 = blockIdx.y * 32;
    int tx = threadIdx.x, ty = threadIdx.y;
    #pragma unroll
    for (int i = 0; i < 4; i++) {
        int k = k0 + ty + i * 8;
        sh[ty + i * 8][tx] = W[(size_t)k * N_DIM + n0 + tx];
    }
    __syncthreads();
    #pragma unroll
    for (int i = 0; i < 4; i++) {
        int nl = ty + i * 8;
        float v = sh[tx][nl];
        __half h = __float2half_rn(v);
        float r = v - __half2float(h);
        size_t n = (size_t)(n0 + nl);
        g_Wh[n * K_DIM + k0 + tx] = h;
        size_t rowb = n * (2 * K_DIM);
        g_WC[rowb + k0 + tx] = q8(v, QS8);            // w*S8  (pairs with xl*SL)
        g_WC[rowb + K_DIM + k0 + tx] = q8(r, QSL);    // wl*SL (pairs with x*S8)
    }
}

// ---------------- main fused GEMM + LLTM ----------------
__global__ __launch_bounds__(256, 1) void lltm_mma_kernel(
    const float* __restrict__ bias,
    const float* __restrict__ old_c,
    float* __restrict__ out)
{
    extern __shared__ char smem[];
    const uint32_t sb = smem_u32(smem);

    const int tid  = threadIdx.x;
    const int wid  = tid >> 5;
    const int lane = tid & 31;
    const int m0 = blockIdx.x * 128;
    const int s0 = blockIdx.y * 32;

    // ---- cp.async plan: 1792 16B chunks / 256 threads = 7 each.
    // A tiles: 512 chunks each (128 rows x 64B); B tiles: 384 each (96 x 64B).
    uint32_t sm_off[7];
    const char* gp[7];
    #pragma unroll
    for (int i = 0; i < 7; i++) {
        int c = tid + i * 256;
        if (c < 1024) {
            int mat = c >> 9;            // 0: Xh (fp16), 1: XC (int8)
            int idx = c & 511;
            int r = idx >> 2, c16 = idx & 3;
            sm_off[i] = (mat ? OFF_AI : OFF_AH) + r * RSB + c16 * 16;
            gp[i] = mat ? (const char*)(g_XC + (size_t)(m0 + r) * (2 * K_DIM) + c16 * 16)
                        : (const char*)(g_Xh + (size_t)(m0 + r) * K_DIM + c16 * 8);
        } else {
            int cc = c - 1024;
            int mat = cc / 384;          // 0: Wh (fp16), 1: WC (int8)
            int idx = cc % 384;
            int r = idx >> 2, c16 = idx & 3;
            int n = (r >> 5) * S_DIM + s0 + (r & 31);   // gate-planar row
            sm_off[i] = (mat ? OFF_BI : OFF_BH) + r * RSB + c16 * 16;
            gp[i] = mat ? (const char*)(g_WC + (size_t)n * (2 * K_DIM) + c16 * 16)
                        : (const char*)(g_Wh + (size_t)n * K_DIM + c16 * 8);
        }
    }
    // per-kt advance: fp16 row 32 elems = 64B; int8 row 64 elems = 64B. Same stride.

    const uint32_t laneOff = (uint32_t)(((lane & 7) + ((lane >> 3) & 1) * 8) * RSB
                                        + (lane >> 4) * 16);
    const uint32_t aBase = sb + wid * (16 * RSB) + laneOff;
    const uint32_t bBase = sb + laneOff;

    float accf[12][4];
    int   acci[12][4];
    #pragma unroll
    for (int j = 0; j < 12; j++)
        #pragma unroll
        for (int e = 0; e < 4; e++) { accf[j][e] = 0.0f; acci[j][e] = 0; }

    #pragma unroll
    for (int st = 0; st < STAGES - 1; st++) {
        #pragma unroll
        for (int i = 0; i < 7; i++)
            cp_async16(sb + st * STAGE_SZ + sm_off[i], gp[i] + (size_t)st * 64);
        cp_commit();
    }

    int rd = 0, wr = STAGES - 1;
    for (int kt = 0; kt < NITER; kt++) {
        cp_wait2();
        __syncthreads();

        if (kt + STAGES - 1 < NITER) {
            #pragma unroll
            for (int i = 0; i < 7; i++)
                cp_async16(sb + wr * STAGE_SZ + sm_off[i],
                           gp[i] + (size_t)(kt + STAGES - 1) * 64);
        }
        cp_commit();

        const uint32_t stg = (uint32_t)(rd * STAGE_SZ);
        #pragma unroll
        for (int kk = 0; kk < 2; kk++) {
            const uint32_t ko = kk * 32;
            uint32_t ah[4], ai[4], bf[6][4];
            // fp16 hi term (k16 per kk)
            ldsm_x4(ah[0], ah[1], ah[2], ah[3], aBase + stg + OFF_AH + ko);
            #pragma unroll
            for (int t = 0; t < 6; t++)
                ldsm_x4(bf[t][0], bf[t][1], bf[t][2], bf[t][3],
                        bBase + stg + OFF_BH + t * (16 * RSB) + ko);
            #pragma unroll
            for (int t = 0; t < 6; t++) {
                mma16816(accf[2 * t],     ah, bf[t][0], bf[t][2]);
                mma16816(accf[2 * t + 1], ah, bf[t][1], bf[t][3]);
            }
            // int8 cross terms (k32 per kk; s8 k32 fragment == f16 k16 fragment as b16 pairs)
            ldsm_x4(ai[0], ai[1], ai[2], ai[3], aBase + stg + OFF_AI + ko);
            #pragma unroll
            for (int t = 0; t < 6; t++) {
                ldsm_x4(bf[t][0], bf[t][1], bf[t][2], bf[t][3],
                        bBase + stg + OFF_BI + t * (16 * RSB) + ko);
                imma16832(acci[2 * t],     ai, bf[t][0], bf[t][2]);
                imma16832(acci[2 * t + 1], ai, bf[t][1], bf[t][3]);
            }
        }
        rd = (rd + 1) & (STAGES - 1);
        wr = (wr + 1) & (STAGES - 1);
    }

    // ---- register-fused LLTM epilogue
    const int row0 = m0 + wid * 16 + (lane >> 2);
    const int scol = (lane & 3) * 2;
    const size_t BS = (size_t)B_DIM * S_DIM;

    #pragma unroll
    for (int j = 0; j < 4; j++) {
        const int sg = s0 + 8 * j + scol;
        const float b0a = __ldg(bias + sg);
        const float b0b = __ldg(bias + sg + 1);
        const float b1a = __ldg(bias + S_DIM + sg);
        const float b1b = __ldg(bias + S_DIM + sg + 1);
        const float b2a = __ldg(bias + 2 * S_DIM + sg);
        const float b2b = __ldg(bias + 2 * S_DIM + sg + 1);
        #pragma unroll
        for (int h = 0; h < 2; h++) {
            const int m = row0 + 8 * h;
            const size_t o = (size_t)m * S_DIM + sg;
            const float2 oc = *(const float2*)(old_c + o);
            float nh[2], nc[2];
            #pragma unroll
            for (int e = 0; e < 2; e++) {
                float g0 = accf[j][2 * h + e]     + (float)acci[j][2 * h + e]     * INV_SS + (e ? b0b : b0a);
                float g1 = accf[j + 4][2 * h + e] + (float)acci[j + 4][2 * h + e] * INV_SS + (e ? b1b : b1a);
                float g2 = accf[j + 8][2 * h + e] + (float)acci[j + 8][2 * h + e] * INV_SS + (e ? b2b : b2a);
                float ig = 1.0f / (1.0f + __expf(-g0));
                float og = 1.0f / (1.0f + __expf(-g1));
                float cand = (g2 > 0.0f) ? g2 : expm1f(g2);
                float ncv = (e ? oc.y : oc.x) + cand * ig;
                nc[e] = ncv;
                nh[e] = tanhf(ncv) * og;
            }
            *(float2*)(out + o) = make_float2(nh[0], nh[1]);
            *(float2*)(out + BS + o) = make_float2(nc[0], nc[1]);
        }
    }
}

// ---------------- launch ----------------
extern "C" void kernel_launch(void* const* d_in, const int* in_sizes, int n_in,
                              void* d_out, int out_size) {
    const float* W     = (const float*)d_in[0];
    const float* bias  = (const float*)d_in[1];
    const float* input = (const float*)d_in[2];
    const float* old_h = (const float*)d_in[3];
    const float* old_c = (const float*)d_in[4];
    float* out = (float*)d_out;

    cudaFuncSetAttribute(lltm_mma_kernel, cudaFuncAttributeMaxDynamicSharedMemorySize, SMEM_TOTAL);

    {
        size_t nthreads = (size_t)B_DIM * K_DIM / 4;
        split_x_kernel<<<(int)(nthreads / 256), 256>>>(input, old_h);
        dim3 g(N_DIM / 32, K_DIM / 32);
        split_w_kernel<<<g, dim3(32, 8)>>>(W);
    }

    dim3 grid(B_DIM / 128, S_DIM / 32);    // (32, 64)
    lltm_mma_kernel<<<grid, 256, SMEM_TOTAL>>>(bias, old_c, out);
}

// round 8
// speedup vs baseline: 1.6119x; 1.6119x over previous
#include <cuda_runtime.h>
#include <cuda_fp16.h>
#include <cuda_fp8.h>
#include <math.h>
#include <stdint.h>

// LLTM, compute_103 baseline PTX (no tcgen05 in this toolchain path).
// gates = concat(old_h, input) @ W + bias, fused activations.
// GEMM = fp16 hi-term (xh*wh) + ONE fp8(e4m3) GEMM for both cross terms,
// accumulated into the SAME f32 accumulators (no extra register pressure):
//   A' = [ e4m3(xl*2^6) | e4m3(xh*2^-6) ],  B' = [ e4m3(wh*2^-6) | e4m3(wl*2^6) ]
//   per-pair product scale = 1  ->  direct f32 accumulation.
// mma.m16n8k16.f16 + mma.m16n8k32.e4m3 + ldmatrix + cp.async 4-stage pipeline.
// CTA tile 128m x 96n, n gate-planar -> register-fused epilogue.
// Shapes: B=4096, F=2048, S=2048, K=4096, N=6144.

#define S_DIM 2048
#define B_DIM 4096
#define K_DIM 4096
#define N_DIM 6144
#define BK    32              // fp16 k per stage (=64B row); fp8 row also 64B (k64 of concat)
#define NITER (K_DIM / BK)    // 128
#define STAGES 4

#define SC_UP   64.0f         // 2^6
#define SC_DN   0.015625f     // 2^-6

// smem: 4 tiles, 64B rows padded to 80B stride (conflict-free ldmatrix).
#define RSB      80
#define OFF_AH   0            // fp16 A, 128 rows
#define OFF_AI   10240        // fp8  A, 128 rows
#define OFF_BH   20480        // fp16 B, 96 rows
#define OFF_BI   28160        // fp8  B, 96 rows
#define STAGE_SZ 35840
#define SMEM_TOTAL (STAGES * STAGE_SZ)   // 143360

// ---------------- device scratch ----------------
__device__ __half   g_Wh[(size_t)N_DIM * K_DIM];
__device__ uint8_t  g_WC[(size_t)N_DIM * 2 * K_DIM];   // [n][0..K): e4m3(wh*2^-6), [K..2K): e4m3(wl*2^6)
__device__ __half   g_Xh[(size_t)B_DIM * K_DIM];
__device__ uint8_t  g_XC[(size_t)B_DIM * 2 * K_DIM];   // [b][0..K): e4m3(xl*2^6),  [K..2K): e4m3(xh*2^-6)

// ---------------- helpers ----------------
__device__ __forceinline__ uint32_t smem_u32(const void* p) {
    uint32_t a;
    asm("{ .reg .u64 t; cvta.to.shared.u64 t, %1; cvt.u32.u64 %0, t; }" : "=r"(a) : "l"(p));
    return a;
}
__device__ __forceinline__ void cp_async16(uint32_t sdst, const void* gsrc) {
    asm volatile("cp.async.cg.shared.global [%0], [%1], 16;" :: "r"(sdst), "l"(gsrc) : "memory");
}
__device__ __forceinline__ void cp_commit() {
    asm volatile("cp.async.commit_group;" ::: "memory");
}
__device__ __forceinline__ void cp_wait2() {
    asm volatile("cp.async.wait_group 2;" ::: "memory");
}
__device__ __forceinline__ void ldsm_x4(uint32_t& r0, uint32_t& r1, uint32_t& r2, uint32_t& r3,
                                        uint32_t addr) {
    asm volatile("ldmatrix.sync.aligned.m8n8.x4.shared.b16 {%0,%1,%2,%3}, [%4];"
                 : "=r"(r0), "=r"(r1), "=r"(r2), "=r"(r3) : "r"(addr));
}
__device__ __forceinline__ void mma16816(float* c, const uint32_t* a, uint32_t b0, uint32_t b1) {
    asm volatile("mma.sync.aligned.m16n8k16.row.col.f32.f16.f16.f32 "
                 "{%0,%1,%2,%3}, {%4,%5,%6,%7}, {%8,%9}, {%0,%1,%2,%3};"
                 : "+f"(c[0]), "+f"(c[1]), "+f"(c[2]), "+f"(c[3])
                 : "r"(a[0]), "r"(a[1]), "r"(a[2]), "r"(a[3]), "r"(b0), "r"(b1));
}
__device__ __forceinline__ void mma_fp8(float* c, const uint32_t* a, uint32_t b0, uint32_t b1) {
    asm volatile("mma.sync.aligned.m16n8k32.row.col.f32.e4m3.e4m3.f32 "
                 "{%0,%1,%2,%3}, {%4,%5,%6,%7}, {%8,%9}, {%0,%1,%2,%3};"
                 : "+f"(c[0]), "+f"(c[1]), "+f"(c[2]), "+f"(c[3])
                 : "r"(a[0]), "r"(a[1]), "r"(a[2]), "r"(a[3]), "r"(b0), "r"(b1));
}
__device__ __forceinline__ uint8_t qf8(float v) {
    __nv_fp8_e4m3 f = __nv_fp8_e4m3(v);
    return *(uint8_t*)&f;
}

// ---------------- pre-pass: X = concat(old_h, input) -> Xh fp16, XC fp8 ----------------
__global__ __launch_bounds__(256) void split_x_kernel(const float* __restrict__ input,
                                                      const float* __restrict__ old_h) {
    size_t idx = ((size_t)blockIdx.x * blockDim.x + threadIdx.x) * 4;
    int b = (int)(idx / K_DIM);
    int k = (int)(idx % K_DIM);
    const float* src = (k < S_DIM) ? old_h + (size_t)b * S_DIM + k
                                   : input + (size_t)b * (K_DIM - S_DIM) + (k - S_DIM);
    float4 v = *(const float4*)src;
    float vv[4] = {v.x, v.y, v.z, v.w};
    union { __half h[4]; uint2 u; } hi;
    uchar4 lo8, hi8;
    unsigned char* lp = (unsigned char*)&lo8;
    unsigned char* hp = (unsigned char*)&hi8;
    #pragma unroll
    for (int e = 0; e < 4; e++) {
        hi.h[e] = __float2half_rn(vv[e]);
        float r = vv[e] - __half2float(hi.h[e]);
        lp[e] = qf8(r * SC_UP);                         // xl * 2^6
        hp[e] = qf8(__half2float(hi.h[e]) * SC_DN);     // xh * 2^-6
    }
    *(uint2*)&g_Xh[idx] = hi.u;
    size_t rowb = (size_t)b * (2 * K_DIM);
    *(uchar4*)&g_XC[rowb + k] = lo8;
    *(uchar4*)&g_XC[rowb + K_DIM + k] = hi8;
}

// ---------------- pre-pass: transpose W[K,N] -> Wh fp16 [N,K], WC fp8 [N,2K] ----------------
__global__ __launch_bounds__(256) void split_w_kernel(const float* __restrict__ W) {
    __shared__ float sh[32][33];
    int n0 = blockIdx.x * 32;
    int k0 = blockIdx.y * 32;
    int tx = threadIdx.x, ty = threadIdx.y;
    #pragma unroll
    for (int i = 0; i < 4; i++) {
        int k = k0 + ty + i * 8;
        sh[ty + i * 8][tx] = W[(size_t)k * N_DIM + n0 + tx];
    }
    __syncthreads();
    #pragma unroll
    for (int i = 0; i < 4; i++) {
        int nl = ty + i * 8;
        float v = sh[tx][nl];
        __half h = __float2half_rn(v);
        float r = v - __half2float(h);
        size_t n = (size_t)(n0 + nl);
        g_Wh[n * K_DIM + k0 + tx] = h;
        size_t rowb = n * (2 * K_DIM);
        g_WC[rowb + k0 + tx] = qf8(__half2float(h) * SC_DN);  // wh * 2^-6 (pairs with xl*2^6)
        g_WC[rowb + K_DIM + k0 + tx] = qf8(r * SC_UP);        // wl * 2^6  (pairs with xh*2^-6)
    }
}

// ---------------- main fused GEMM + LLTM ----------------
__global__ __launch_bounds__(256, 1) void lltm_mma_kernel(
    const float* __restrict__ bias,
    const float* __restrict__ old_c,
    float* __restrict__ out)
{
    extern __shared__ char smem[];
    const uint32_t sb = smem_u32(smem);

    const int tid  = threadIdx.x;
    const int wid  = tid >> 5;
    const int lane = tid & 31;
    const int m0 = blockIdx.x * 128;
    const int s0 = blockIdx.y * 32;

    // ---- cp.async plan: 1792 16B chunks / 256 threads = 7 each.
    uint32_t sm_off[7];
    const char* gp[7];
    #pragma unroll
    for (int i = 0; i < 7; i++) {
        int c = tid + i * 256;
        if (c < 1024) {
            int mat = c >> 9;            // 0: Xh (fp16), 1: XC (fp8)
            int idx = c & 511;
            int r = idx >> 2, c16 = idx & 3;
            sm_off[i] = (mat ? OFF_AI : OFF_AH) + r * RSB + c16 * 16;
            gp[i] = mat ? (const char*)(g_XC + (size_t)(m0 + r) * (2 * K_DIM) + c16 * 16)
                        : (const char*)(g_Xh + (size_t)(m0 + r) * K_DIM + c16 * 8);
        } else {
            int cc = c - 1024;
            int mat = cc / 384;          // 0: Wh (fp16), 1: WC (fp8)
            int idx = cc % 384;
            int r = idx >> 2, c16 = idx & 3;
            int n = (r >> 5) * S_DIM + s0 + (r & 31);   // gate-planar row
            sm_off[i] = (mat ? OFF_BI : OFF_BH) + r * RSB + c16 * 16;
            gp[i] = mat ? (const char*)(g_WC + (size_t)n * (2 * K_DIM) + c16 * 16)
                        : (const char*)(g_Wh + (size_t)n * K_DIM + c16 * 8);
        }
    }
    // per-kt advance: fp16 row 32 elems = 64B; fp8 row 64 elems = 64B. Same stride.

    const uint32_t laneOff = (uint32_t)(((lane & 7) + ((lane >> 3) & 1) * 8) * RSB
                                        + (lane >> 4) * 16);
    const uint32_t aBase = sb + wid * (16 * RSB) + laneOff;
    const uint32_t bBase = sb + laneOff;

    float accf[12][4];
    #pragma unroll
    for (int j = 0; j < 12; j++)
        #pragma unroll
        for (int e = 0; e < 4; e++) accf[j][e] = 0.0f;

    #pragma unroll
    for (int st = 0; st < STAGES - 1; st++) {
        #pragma unroll
        for (int i = 0; i < 7; i++)
            cp_async16(sb + st * STAGE_SZ + sm_off[i], gp[i] + (size_t)st * 64);
        cp_commit();
    }

    int rd = 0, wr = STAGES - 1;
    for (int kt = 0; kt < NITER; kt++) {
        cp_wait2();
        __syncthreads();

        if (kt + STAGES - 1 < NITER) {
            #pragma unroll
            for (int i = 0; i < 7; i++)
                cp_async16(sb + wr * STAGE_SZ + sm_off[i],
                           gp[i] + (size_t)(kt + STAGES - 1) * 64);
        }
        cp_commit();

        const uint32_t stg = (uint32_t)(rd * STAGE_SZ);
        #pragma unroll
        for (int kk = 0; kk < 2; kk++) {
            const uint32_t ko = kk * 32;
            uint32_t ah[4], ai[4], bf[6][4];
            // fp16 hi term (k16 per kk)
            ldsm_x4(ah[0], ah[1], ah[2], ah[3], aBase + stg + OFF_AH + ko);
            #pragma unroll
            for (int t = 0; t < 6; t++)
                ldsm_x4(bf[t][0], bf[t][1], bf[t][2], bf[t][3],
                        bBase + stg + OFF_BH + t * (16 * RSB) + ko);
            #pragma unroll
            for (int t = 0; t < 6; t++) {
                mma16816(accf[2 * t],     ah, bf[t][0], bf[t][2]);
                mma16816(accf[2 * t + 1], ah, bf[t][1], bf[t][3]);
            }
            // fp8 cross terms (k32 of concat per kk; same byte layout as proven s8 path)
            ldsm_x4(ai[0], ai[1], ai[2], ai[3], aBase + stg + OFF_AI + ko);
            #pragma unroll
            for (int t = 0; t < 6; t++) {
                ldsm_x4(bf[t][0], bf[t][1], bf[t][2], bf[t][3],
                        bBase + stg + OFF_BI + t * (16 * RSB) + ko);
                mma_fp8(accf[2 * t],     ai, bf[t][0], bf[t][2]);
                mma_fp8(accf[2 * t + 1], ai, bf[t][1], bf[t][3]);
            }
        }
        rd = (rd + 1) & (STAGES - 1);
        wr = (wr + 1) & (STAGES - 1);
    }

    // ---- register-fused LLTM epilogue
    const int row0 = m0 + wid * 16 + (lane >> 2);
    const int scol = (lane & 3) * 2;
    const size_t BS = (size_t)B_DIM * S_DIM;

    #pragma unroll
    for (int j = 0; j < 4; j++) {
        const int sg = s0 + 8 * j + scol;
        const float b0a = __ldg(bias + sg);
        const float b0b = __ldg(bias + sg + 1);
        const float b1a = __ldg(bias + S_DIM + sg);
        const float b1b = __ldg(bias + S_DIM + sg + 1);
        const float b2a = __ldg(bias + 2 * S_DIM + sg);
        const float b2b = __ldg(bias + 2 * S_DIM + sg + 1);
        #pragma unroll
        for (int h = 0; h < 2; h++) {
            const int m = row0 + 8 * h;
            const size_t o = (size_t)m * S_DIM + sg;
            const float2 oc = *(const float2*)(old_c + o);
            float nh[2], nc[2];
            #pragma unroll
            for (int e = 0; e < 2; e++) {
                float g0 = accf[j][2 * h + e]     + (e ? b0b : b0a);
                float g1 = accf[j + 4][2 * h + e] + (e ? b1b : b1a);
                float g2 = accf[j + 8][2 * h + e] + (e ? b2b : b2a);
                float ig = 1.0f / (1.0f + __expf(-g0));
                float og = 1.0f / (1.0f + __expf(-g1));
                float cand = (g2 > 0.0f) ? g2 : expm1f(g2);
                float ncv = (e ? oc.y : oc.x) + cand * ig;
                nc[e] = ncv;
                nh[e] = tanhf(ncv) * og;
            }
            *(float2*)(out + o) = make_float2(nh[0], nh[1]);
            *(float2*)(out + BS + o) = make_float2(nc[0], nc[1]);
        }
    }
}

// ---------------- launch ----------------
extern "C" void kernel_launch(void* const* d_in, const int* in_sizes, int n_in,
                              void* d_out, int out_size) {
    const float* W     = (const float*)d_in[0];
    const float* bias  = (const float*)d_in[1];
    const float* input = (const float*)d_in[2];
    const float* old_h = (const float*)d_in[3];
    const float* old_c = (const float*)d_in[4];
    float* out = (float*)d_out;

    cudaFuncSetAttribute(lltm_mma_kernel, cudaFuncAttributeMaxDynamicSharedMemorySize, SMEM_TOTAL);

    {
        size_t nthreads = (size_t)B_DIM * K_DIM / 4;
        split_x_kernel<<<(int)(nthreads / 256), 256>>>(input, old_h);
        dim3 g(N_DIM / 32, K_DIM / 32);
        split_w_kernel<<<g, dim3(32, 8)>>>(W);
    }

    dim3 grid(B_DIM / 128, S_DIM / 32);    // (32, 64)
    lltm_mma_kernel<<<grid, 256, SMEM_TOTAL>>>(bias, old_c, out);
}

// round 10
// speedup vs baseline: 1.9602x; 1.2161x over previous
#include <cuda_runtime.h>
#include <cuda_fp16.h>
#include <math.h>
#include <stdint.h>

// LLTM, compute_103 baseline PTX. gates = concat(old_h, input) @ W + bias, fused.
// GEMM: fp16x3 split emulation (xh*wh in f32-acc; xh*wl + xl*wh in f16-acc mma,
// folded into f32 at the end — cross sums are ~0.01 so f16 accumulation is safe).
// mma.m16n8k16 + ldmatrix + cp.async 4-stage pipeline.
// CTA tile 128m x 96n, n gate-planar -> register-fused epilogue.
// Shapes: B=4096, F=2048, S=2048, K=4096, N=6144.

#define S_DIM 2048
#define B_DIM 4096
#define K_DIM 4096
#define N_DIM 6144
#define BK    32
#define NITER (K_DIM / BK)     // 128
#define STAGES 4

#define RSB      80
#define OFF_AH   0
#define OFF_AL   10240
#define OFF_BH   20480
#define OFF_BL   28160
#define STAGE_SZ 35840
#define SMEM_TOTAL (STAGES * STAGE_SZ)   // 143360

// ---------------- device scratch ----------------
__device__ __half g_Wh1[(size_t)N_DIM * K_DIM];
__device__ __half g_Wl2[(size_t)N_DIM * K_DIM];
__device__ __half g_Xh1[(size_t)B_DIM * K_DIM];
__device__ __half g_Xl2[(size_t)B_DIM * K_DIM];

// ---------------- helpers ----------------
__device__ __forceinline__ uint32_t smem_u32(const void* p) {
    uint32_t a;
    asm("{ .reg .u64 t; cvta.to.shared.u64 t, %1; cvt.u32.u64 %0, t; }" : "=r"(a) : "l"(p));
    return a;
}
__device__ __forceinline__ void cp_async16(uint32_t sdst, const void* gsrc) {
    asm volatile("cp.async.cg.shared.global [%0], [%1], 16;" :: "r"(sdst), "l"(gsrc) : "memory");
}
__device__ __forceinline__ void cp_commit() {
    asm volatile("cp.async.commit_group;" ::: "memory");
}
__device__ __forceinline__ void cp_wait2() {
    asm volatile("cp.async.wait_group 2;" ::: "memory");
}
__device__ __forceinline__ void ldsm_x4(uint32_t& r0, uint32_t& r1, uint32_t& r2, uint32_t& r3,
                                        uint32_t addr) {
    asm volatile("ldmatrix.sync.aligned.m8n8.x4.shared.b16 {%0,%1,%2,%3}, [%4];"
                 : "=r"(r0), "=r"(r1), "=r"(r2), "=r"(r3) : "r"(addr));
}
__device__ __forceinline__ void mma16816(float* c, const uint32_t* a, uint32_t b0, uint32_t b1) {
    asm volatile("mma.sync.aligned.m16n8k16.row.col.f32.f16.f16.f32 "
                 "{%0,%1,%2,%3}, {%4,%5,%6,%7}, {%8,%9}, {%0,%1,%2,%3};"
                 : "+f"(c[0]), "+f"(c[1]), "+f"(c[2]), "+f"(c[3])
                 : "r"(a[0]), "r"(a[1]), "r"(a[2]), "r"(a[3]), "r"(b0), "r"(b1));
}
// f16-accumulate variant: C/D = 2x u32 (4 halves).
__device__ __forceinline__ void mma16816h(uint32_t* c, const uint32_t* a, uint32_t b0, uint32_t b1) {
    asm volatile("mma.sync.aligned.m16n8k16.row.col.f16.f16.f16.f16 "
                 "{%0,%1}, {%2,%3,%4,%5}, {%6,%7}, {%0,%1};"
                 : "+r"(c[0]), "+r"(c[1])
                 : "r"(a[0]), "r"(a[1]), "r"(a[2]), "r"(a[3]), "r"(b0), "r"(b1));
}

// ---------------- pre-pass: split X = concat(old_h, input) into fp16 hi/lo ----------------
__global__ __launch_bounds__(256) void split_x_kernel(const float* __restrict__ input,
                                                      const float* __restrict__ old_h) {
    size_t idx = ((size_t)blockIdx.x * blockDim.x + threadIdx.x) * 4;
    int b = (int)(idx / K_DIM);
    int k = (int)(idx % K_DIM);
    const float* src = (k < S_DIM) ? old_h + (size_t)b * S_DIM + k
                                   : input + (size_t)b * (K_DIM - S_DIM) + (k - S_DIM);
    float4 v = *(const float4*)src;
    float vv[4] = {v.x, v.y, v.z, v.w};
    union { __half h[4]; uint2 u; } hi, lo;
    #pragma unroll
    for (int e = 0; e < 4; e++) {
        hi.h[e] = __float2half_rn(vv[e]);
        lo.h[e] = __float2half_rn(vv[e] - __half2float(hi.h[e]));
    }
    *(uint2*)&g_Xh1[idx] = hi.u;
    *(uint2*)&g_Xl2[idx] = lo.u;
}

// ---------------- pre-pass: transpose W[K,N] -> Wt[N,K] fp16 hi/lo ----------------
__global__ __launch_bounds__(256) void split_w_kernel(const float* __restrict__ W) {
    __shared__ float sh[32][33];
    int n0 = blockIdx.x * 32;
    int k0 = blockIdx.y * 32;
    int tx = threadIdx.x, ty = threadIdx.y;
    #pragma unroll
    for (int i = 0; i < 4; i++) {
        int k = k0 + ty + i * 8;
        sh[ty + i * 8][tx] = W[(size_t)k * N_DIM + n0 + tx];
    }
    __syncthreads();
    #pragma unroll
    for (int i = 0; i < 4; i++) {
        int nl = ty + i * 8;
        float v = sh[tx][nl];
        __half hi = __float2half_rn(v);
        __half lo = __float2half_rn(v - __half2float(hi));
        size_t off = (size_t)(n0 + nl) * K_DIM + k0 + tx;
        g_Wh1[off] = hi;
        g_Wl2[off] = lo;
    }
}

// ---------------- main fused GEMM + LLTM ----------------
__global__ __launch_bounds__(256, 1) void lltm_mma_kernel(
    const float* __restrict__ bias,
    const float* __restrict__ old_c,
    float* __restrict__ out)
{
    extern __shared__ char smem[];
    const uint32_t sb = smem_u32(smem);

    const int tid  = threadIdx.x;
    const int wid  = tid >> 5;
    const int lane = tid & 31;
    const int m0 = blockIdx.x * 128;
    const int s0 = blockIdx.y * 32;

    // ---- cp.async plan: 1792 16B chunks / 256 threads = 7 each
    uint32_t sm_off[7];
    const char* gp[7];
    #pragma unroll
    for (int i = 0; i < 7; i++) {
        int c = tid + i * 256;
        if (c < 1024) {
            int mat = c >> 9;            // 0: Xh1, 1: Xl2
            int idx = c & 511;
            int r = idx >> 2, c16 = idx & 3;
            sm_off[i] = (mat ? OFF_AL : OFF_AH) + r * RSB + c16 * 16;
            const __half* base = mat ? g_Xl2 : g_Xh1;
            gp[i] = (const char*)(base + (size_t)(m0 + r) * K_DIM + c16 * 8);
        } else {
            int cc = c - 1024;
            int mat = cc / 384;          // 0: Wh1, 1: Wl2
            int idx = cc % 384;
            int r = idx >> 2, c16 = idx & 3;
            int n = (r >> 5) * S_DIM + s0 + (r & 31);   // gate-planar row
            sm_off[i] = (mat ? OFF_BL : OFF_BH) + r * RSB + c16 * 16;
            const __half* base = mat ? g_Wl2 : g_Wh1;
            gp[i] = (const char*)(base + (size_t)n * K_DIM + c16 * 8);
        }
    }

    const uint32_t laneOff = (uint32_t)(((lane & 7) + ((lane >> 3) & 1) * 8) * RSB
                                        + (lane >> 4) * 16);
    const uint32_t aBase = sb + wid * (16 * RSB) + laneOff;
    const uint32_t bBase = sb + laneOff;

    float    accf[12][4];        // hi term, f32 accum
    uint32_t accx[12][2];        // cross terms, packed f16x2 accum (zero = 0u)
    #pragma unroll
    for (int j = 0; j < 12; j++) {
        #pragma unroll
        for (int e = 0; e < 4; e++) accf[j][e] = 0.0f;
        accx[j][0] = 0u; accx[j][1] = 0u;
    }

    #pragma unroll
    for (int st = 0; st < STAGES - 1; st++) {
        #pragma unroll
        for (int i = 0; i < 7; i++)
            cp_async16(sb + st * STAGE_SZ + sm_off[i], gp[i] + (size_t)st * (BK * 2));
        cp_commit();
    }

    int rd = 0, wr = STAGES - 1;
    for (int kt = 0; kt < NITER; kt++) {
        cp_wait2();
        __syncthreads();

        if (kt + STAGES - 1 < NITER) {
            #pragma unroll
            for (int i = 0; i < 7; i++)
                cp_async16(sb + wr * STAGE_SZ + sm_off[i],
                           gp[i] + (size_t)(kt + STAGES - 1) * (BK * 2));
        }
        cp_commit();

        const uint32_t stg = (uint32_t)(rd * STAGE_SZ);
        #pragma unroll
        for (int kk = 0; kk < 2; kk++) {
            const uint32_t ko = kk * 32;
            uint32_t ah[4], al[4], bf[6][4];
            ldsm_x4(ah[0], ah[1], ah[2], ah[3], aBase + stg + OFF_AH + ko);
            ldsm_x4(al[0], al[1], al[2], al[3], aBase + stg + OFF_AL + ko);
            #pragma unroll
            for (int t = 0; t < 6; t++)
                ldsm_x4(bf[t][0], bf[t][1], bf[t][2], bf[t][3],
                        bBase + stg + OFF_BH + t * (16 * RSB) + ko);
            // term 1: xh*wh -> f32 acc
            #pragma unroll
            for (int t = 0; t < 6; t++) {
                mma16816(accf[2 * t],     ah, bf[t][0], bf[t][2]);
                mma16816(accf[2 * t + 1], ah, bf[t][1], bf[t][3]);
            }
            // term 3: xl*wh -> f16 acc
            #pragma unroll
            for (int t = 0; t < 6; t++) {
                mma16816h(accx[2 * t],     al, bf[t][0], bf[t][2]);
                mma16816h(accx[2 * t + 1], al, bf[t][1], bf[t][3]);
            }
            // term 2: xh*wl -> f16 acc
            #pragma unroll
            for (int t = 0; t < 6; t++) {
                ldsm_x4(bf[t][0], bf[t][1], bf[t][2], bf[t][3],
                        bBase + stg + OFF_BL + t * (16 * RSB) + ko);
                mma16816h(accx[2 * t],     ah, bf[t][0], bf[t][2]);
                mma16816h(accx[2 * t + 1], ah, bf[t][1], bf[t][3]);
            }
        }
        rd = (rd + 1) & (STAGES - 1);
        wr = (wr + 1) & (STAGES - 1);
    }

    // ---- register-fused LLTM epilogue (fold f16 cross acc into f32)
    const int row0 = m0 + wid * 16 + (lane >> 2);
    const int scol = (lane & 3) * 2;
    const size_t BS = (size_t)B_DIM * S_DIM;

    #pragma unroll
    for (int j = 0; j < 4; j++) {
        const int sg = s0 + 8 * j + scol;
        const float b0a = __ldg(bias + sg);
        const float b0b = __ldg(bias + sg + 1);
        const float b1a = __ldg(bias + S_DIM + sg);
        const float b1b = __ldg(bias + S_DIM + sg + 1);
        const float b2a = __ldg(bias + 2 * S_DIM + sg);
        const float b2b = __ldg(bias + 2 * S_DIM + sg + 1);
        #pragma unroll
        for (int h = 0; h < 2; h++) {
            const int m = row0 + 8 * h;
            const size_t o = (size_t)m * S_DIM + sg;
            const float2 oc = *(const float2*)(old_c + o);
            const __half2 x0 = *(const __half2*)&accx[j][h];
            const __half2 x1 = *(const __half2*)&accx[j + 4][h];
            const __half2 x2 = *(const __half2*)&accx[j + 8][h];
            float nh[2], nc[2];
            #pragma unroll
            for (int e = 0; e < 2; e++) {
                float c0 = __half2float(e ? x0.y : x0.x);
                float c1 = __half2float(e ? x1.y : x1.x);
                float c2 = __half2float(e ? x2.y : x2.x);
                float g0 = accf[j][2 * h + e]     + c0 + (e ? b0b : b0a);
                float g1 = accf[j + 4][2 * h + e] + c1 + (e ? b1b : b1a);
                float g2 = accf[j + 8][2 * h + e] + c2 + (e ? b2b : b2a);
                float ig = 1.0f / (1.0f + __expf(-g0));
                float og = 1.0f / (1.0f + __expf(-g1));
                float cand = (g2 > 0.0f) ? g2 : expm1f(g2);
                float ncv = (e ? oc.y : oc.x) + cand * ig;
                nc[e] = ncv;
                nh[e] = tanhf(ncv) * og;
            }
            *(float2*)(out + o) = make_float2(nh[0], nh[1]);
            *(float2*)(out + BS + o) = make_float2(nc[0], nc[1]);
        }
    }
}

// ---------------- launch ----------------
extern "C" void kernel_launch(void* const* d_in, const int* in_sizes, int n_in,
                              void* d_out, int out_size) {
    const float* W     = (const float*)d_in[0];
    const float* bias  = (const float*)d_in[1];
    const float* input = (const float*)d_in[2];
    const float* old_h = (const float*)d_in[3];
    const float* old_c = (const float*)d_in[4];
    float* out = (float*)d_out;

    cudaFuncSetAttribute(lltm_mma_kernel, cudaFuncAttributeMaxDynamicSharedMemorySize, SMEM_TOTAL);

    {
        size_t nthreads = (size_t)B_DIM * K_DIM / 4;
        split_x_kernel<<<(int)(nthreads / 256), 256>>>(input, old_h);
        dim3 g(N_DIM / 32, K_DIM / 32);
        split_w_kernel<<<g, dim3(32, 8)>>>(W);
    }

    dim3 grid(B_DIM / 128, S_DIM / 32);    // (32, 64)
    lltm_mma_kernel<<<grid, 256, SMEM_TOTAL>>>(bias, old_c, out);
}